// round 7
// baseline (speedup 1.0000x reference)
#include <cuda_runtime.h>

#define N_NODES 50000
#define N_EDGES 200000
#define F_IN 100
#define HID 1024

#define NBLK 592                 // 4 blocks/SM on 148 SMs -> single wave guaranteed
#define NTHR 256
#define NT   (NBLK * NTHR)       // 151552 threads
#define NW   (NBLK * (NTHR/32))  // 4736 warps

// Scratch (no device allocation allowed)
__device__ float g_w[F_IN];
__device__ float g_c;
__device__ float g_deg[N_NODES];
__device__ float g_dinv[N_NODES];
__device__ float g_s[N_NODES];
__device__ float g_p[N_NODES];
__device__ int   g_is64;

// grid barrier state (zero-init; count returns to 0 after each barrier,
// gen monotonically increases across replays -> deterministic behavior)
__device__ unsigned g_count;
__device__ volatile unsigned g_gen;

__device__ __forceinline__ void grid_barrier() {
    __syncthreads();
    if (threadIdx.x == 0) {
        __threadfence();                       // make phase writes visible
        unsigned my = g_gen;                   // read gen BEFORE arriving
        if (atomicAdd(&g_count, 1u) == NBLK - 1u) {
            g_count = 0;
            __threadfence();
            g_gen = my + 1u;                   // release
        } else {
            while (g_gen == my) { }            // spin (volatile load)
        }
    }
    __syncthreads();
}

__device__ __forceinline__ int load_edge(const int* __restrict__ ebuf,
                                         long long pos, bool is64) {
    if (is64) return ((const int2*)ebuf)[pos].x;
    return ebuf[pos];
}

__global__ void __launch_bounds__(NTHR, 4)
gcn_persistent(const float* __restrict__ x,
               const int*   __restrict__ ebuf,
               const float* __restrict__ W1,
               const float* __restrict__ b1,
               const float* __restrict__ Wh,
               const float* __restrict__ bh,
               float* __restrict__ out) {
    const int blk = blockIdx.x;
    const int t   = threadIdx.x;
    const int gid = blk * NTHR + t;
    __shared__ float sred[NTHR];
    __shared__ float sw[F_IN];

    // ---------------- Phase A: deg init + fold + dtype detect ----------------
    for (int i = gid; i < N_NODES; i += NT) g_deg[i] = 1.0f;   // self loop

    if (blk <= F_IN) {          // blocks 0..99: w rows; block 100: c
        float acc = 0.f;
        if (blk < F_IN) {
            const float* row = W1 + (long long)blk * HID;
            for (int k = t; k < HID; k += NTHR) acc += row[k] * Wh[k];
        } else {
            for (int k = t; k < HID; k += NTHR) acc += b1[k] * Wh[k];
        }
        sred[t] = acc;
        __syncthreads();
        for (int s = NTHR / 2; s > 0; s >>= 1) {
            if (t < s) sred[t] += sred[t + s];
            __syncthreads();
        }
        if (t == 0) {
            if (blk < F_IN) g_w[blk] = sred[0];
            else            g_c     = sred[0] + bh[0];
        }
    } else if (blk == F_IN + 1) {
        // int64-LE values < 50000 => every odd 32-bit word is 0
        __shared__ int nz;
        if (t == 0) nz = 0;
        __syncthreads();
        if (t < 128 && ebuf[2 * t + 1] != 0) nz = 1;
        __syncthreads();
        if (t == 0) g_is64 = nz ? 0 : 1;
    }

    grid_barrier();   // w, c, deg=1, is64 visible

    // ---------------- Phase B: degree atomics + node dots --------------------
    const bool is64 = (g_is64 != 0);

    for (int e = gid; e < N_EDGES; e += NT) {
        int dst = load_edge(ebuf, (long long)N_EDGES + e, is64);
        if ((unsigned)dst < N_NODES) atomicAdd(&g_deg[dst], 1.0f);
    }

    for (int i = t; i < F_IN; i += NTHR) sw[i] = g_w[i];
    __syncthreads();

    const int warp = gid >> 5;
    const int lane = t & 31;
    for (int n = warp; n < N_NODES; n += NW) {
        const float* xr = x + (long long)n * F_IN;
        float acc = xr[lane]      * sw[lane]
                  + xr[lane + 32] * sw[lane + 32]
                  + xr[lane + 64] * sw[lane + 64];
        if (lane < 4) acc += xr[lane + 96] * sw[lane + 96];
        #pragma unroll
        for (int o = 16; o > 0; o >>= 1)
            acc += __shfl_down_sync(0xffffffffu, acc, o);
        if (lane == 0) g_s[n] = acc;
    }

    grid_barrier();   // deg, s complete

    // ---------------- Phase C: node finalize ---------------------------------
    for (int n = gid; n < N_NODES; n += NT) {
        float d = rsqrtf(g_deg[n]);
        float s = g_s[n];
        g_dinv[n] = d;
        g_p[n]    = s * d;
        out[n]    = g_c + s * d * d;   // self-loop message + folded bias
    }

    grid_barrier();   // p, dinv, out-init complete

    // ---------------- Phase D: edge scatter ----------------------------------
    for (int e = gid; e < N_EDGES; e += NT) {
        int s = load_edge(ebuf, e, is64);
        int d = load_edge(ebuf, (long long)N_EDGES + e, is64);
        if ((unsigned)s < N_NODES && (unsigned)d < N_NODES)
            atomicAdd(&out[d], g_p[s] * g_dinv[d]);
    }
}

extern "C" void kernel_launch(void* const* d_in, const int* in_sizes, int n_in,
                              void* d_out, int out_size) {
    const float* state = (const float*)d_in[0];  // [N, 100, 1] f32
    const int*   ebuf  = (const int*)  d_in[1];  // [2, 200000] int32/int64 layout
    const float* W1    = (const float*)d_in[2];  // [100, 1024]
    const float* b1    = (const float*)d_in[3];  // [1024]
    const float* Wh    = (const float*)d_in[4];  // [1024, 1]
    const float* bh    = (const float*)d_in[5];  // [1]
    float* out = (float*)d_out;                  // [N, 1]

    gcn_persistent<<<NBLK, NTHR>>>(state, ebuf, W1, b1, Wh, bh, out);
}